// round 3
// baseline (speedup 1.0000x reference)
#include <cuda_runtime.h>
#include <cstdint>

#define BATCH 32
#define SEQ   512
#define DIMK  64
#define NDIAG 1023          // 2*SEQ - 1 diagonals (p = 0..1022)
#define DPITCH 1024
#define STAGES 8            // pipeline stages per batch (64 rows each)
#define BIGF  1e30f
#define L2E   1.4426950408889634f
#define LN2   0.6931471805599453f

// Diagonal-major distance scratch: Ddiag[b][p][i] = D[b, i, p-i]  (64 MB)
__device__ float g_Ddiag[BATCH * DPITCH * SEQ];
// Inter-stage boundary rings + group flags (L2-resident, tiny)
__device__ float    g_bnd[BATCH][STAGES][DPITCH];
__device__ unsigned g_flag[BATCH][STAGES];

// ---------------------------------------------------------------------------
// Phase 1: D = x2 + y2 - 2 x.y, written diagonal-major with coalesced stores.
// Also resets the DP flags for this run (graph-replay safe).
// ---------------------------------------------------------------------------
#define TI 128
#define TJ 128
#define YS_STRIDE 132
#define DST_STRIDE 9

__global__ __launch_bounds__(128) void gemm_diag_kernel(
    const float* __restrict__ X, const float* __restrict__ Y) {
  const int t  = threadIdx.x;
  const int i0 = blockIdx.x * TI;
  const int j0 = blockIdx.y * TJ;
  const int b  = blockIdx.z;

  if (blockIdx.x == 0 && blockIdx.y == 0 && t < STAGES) g_flag[b][t] = 0;

  __shared__ float Ys[DIMK * YS_STRIDE];  // [k][j]
  __shared__ float y2s[TJ];
  __shared__ float Dst[TI * DST_STRIDE];

  const float* Xb = X + ((size_t)b * SEQ + i0) * DIMK;
  const float* Yb = Y + ((size_t)b * SEQ + j0) * DIMK;

  for (int e = t; e < TJ * DIMK; e += 128) {
    int j = e >> 6;
    int k = e & 63;
    Ys[k * YS_STRIDE + j] = Yb[e];
  }

  float xr[DIMK];
  float x2 = 0.f;
#pragma unroll
  for (int k4 = 0; k4 < DIMK; k4 += 4) {
    float4 v = *reinterpret_cast<const float4*>(Xb + (size_t)t * DIMK + k4);
    xr[k4] = v.x; xr[k4 + 1] = v.y; xr[k4 + 2] = v.z; xr[k4 + 3] = v.w;
  }
#pragma unroll
  for (int k = 0; k < DIMK; k++) x2 += xr[k] * xr[k];

  __syncthreads();

  {
    float a = 0.f;
#pragma unroll
    for (int k = 0; k < DIMK; k++) {
      float yv = Ys[k * YS_STRIDE + t];
      a += yv * yv;
    }
    y2s[t] = a;
  }
  __syncthreads();

  float* gout = g_Ddiag + (size_t)b * (DPITCH * SEQ);
  const int w = t >> 5, lane = t & 31;

  for (int jb = 0; jb < TJ / 8; jb++) {
    float acc[8];
#pragma unroll
    for (int m = 0; m < 8; m++) acc[m] = 0.f;

#pragma unroll
    for (int k = 0; k < DIMK; k++) {
      const float4 ya = *reinterpret_cast<const float4*>(&Ys[k * YS_STRIDE + jb * 8]);
      const float4 yb = *reinterpret_cast<const float4*>(&Ys[k * YS_STRIDE + jb * 8 + 4]);
      const float xv = xr[k];
      acc[0] += xv * ya.x; acc[1] += xv * ya.y;
      acc[2] += xv * ya.z; acc[3] += xv * ya.w;
      acc[4] += xv * yb.x; acc[5] += xv * yb.y;
      acc[6] += xv * yb.z; acc[7] += xv * yb.w;
    }

#pragma unroll
    for (int m = 0; m < 8; m++) {
      Dst[t * DST_STRIDE + m] = x2 + y2s[jb * 8 + m] - 2.f * acc[m];
    }
    __syncthreads();

    const int p0 = i0 + j0 + jb * 8;
    for (int dbase = w * 4; dbase < TI + 8 - 1; dbase += 16) {
      int d = dbase + (lane >> 3);
      int q = lane & 7;
      if (d < TI + 8 - 1) {
        int lo = d - 7 < 0 ? 0 : d - 7;
        int hi = d < TI - 1 ? d : TI - 1;
        int irow = lo + q;
        if (irow <= hi) {
          gout[(size_t)(p0 + d) * SEQ + (i0 + irow)] =
              Dst[irow * DST_STRIDE + (d - irow)];
        }
      }
    }
    __syncthreads();
  }
}

// ---------------------------------------------------------------------------
// Phase 2: wavefront DP, 8 one-warp CTAs per batch (64 rows each, 2 rows per
// thread). No __syncthreads. Inter-stage boundary via L2 ring + release/
// acquire flags, 2 groups of skew. Base-2 scaled domain.
// ---------------------------------------------------------------------------
__device__ __forceinline__ float ex2f(float x) {
  float r; asm("ex2.approx.f32 %0, %1;" : "=f"(r) : "f"(x)); return r;
}
__device__ __forceinline__ float lg2f(float x) {
  float r; asm("lg2.approx.f32 %0, %1;" : "=f"(r) : "f"(x)); return r;
}
// softmin (base-2 domain): 2 EX2 + 1 LG2 via exact min/median/max.
__device__ __forceinline__ float softmin3s(float a, float b, float c) {
  float u = fminf(a, b), v = fmaxf(a, b);
  float mn = fminf(u, c);
  float mx = fmaxf(v, c);
  float md = fmaxf(u, fminf(v, c));
  float sum = 1.0f + ex2f(mn - md) + ex2f(mn - mx);
  return mn - lg2f(sum);
}

__global__ __launch_bounds__(32) void softdtw_dp_kernel(float* __restrict__ out) {
  const int b = blockIdx.x;
  const int s = blockIdx.y;
  const int lane = (int)threadIdx.x;
  const int row0 = s * 64 + 2 * lane;     // thread owns rows row0, row0+1

  const float* __restrict__ base =
      g_Ddiag + (size_t)b * (DPITCH * SEQ) + row0;
  const float* __restrict__ bprev = &g_bnd[b][(s > 0) ? (s - 1) : 0][0];
  float* __restrict__ bmy = &g_bnd[b][s][0];
  const unsigned* fprev = &g_flag[b][(s > 0) ? (s - 1) : 0];
  unsigned* fmy = &g_flag[b][s];

  float v1a = BIGF, v1b = BIGF, v2a = BIGF, v2b = BIGF;
  float rcarry = BIGF;                    // bnd[p-2] carried into each group
  float rv[8], rvn[8];
#pragma unroll
  for (int j = 0; j < 8; j++) { rv[j] = BIGF; rvn[j] = BIGF; }

  // --- D prefetch (2 groups ahead), clamped in-bounds ---
  float2 cur[8], nxt[8], pf[8];
#define LOADD(G, DST)                                                       \
  {                                                                         \
    _Pragma("unroll") for (int j = 0; j < 8; j++) {                         \
      int p = 8 * (G) + j; if (p > 1022) p = 1022;                          \
      (DST)[j] = *reinterpret_cast<const float2*>(base + (size_t)p * SEQ);  \
    }                                                                       \
  }
  LOADD(0, cur);
  LOADD(1, nxt);

#define WAITFLAG(NEED)                                                      \
  {                                                                         \
    unsigned f_;                                                            \
    for (;;) {                                                              \
      asm volatile("ld.acquire.gpu.global.b32 %0, [%1];"                   \
                   : "=r"(f_) : "l"(fprev) : "memory");                     \
      if ((int)f_ >= (NEED)) break;                                         \
      __nanosleep(32);                                                      \
    }                                                                       \
  }
  // ring values for group G: rv[j] = bnd[8G - 1 + j]
#define LOADRING(G, DST)                                                    \
  if (lane == 0) {                                                          \
    _Pragma("unroll") for (int j = 0; j < 8; j++) {                         \
      int idx = 8 * (G) - 1 + j;                                            \
      (DST)[j] = (idx >= 0) ? bprev[idx] : BIGF;                            \
    }                                                                       \
  }

  if (s > 0) { WAITFLAG(1); LOADRING(0, rv); }

  for (int g = 0; g < 128; ++g) {
    // prefetch NEXT group's ring (needs producer 2 groups ahead) + D
    if (s > 0 && g + 1 < 128) {
      WAITFLAG(g + 2);
      LOADRING(g + 1, rvn);
    }
    LOADD(g + 2, pf);

#pragma unroll
    for (int j = 0; j < 8; j++) {
      const int p = 8 * g + j;
      float nb1 = __shfl_up_sync(0xffffffffu, v1b, 1);
      float nb2 = __shfl_up_sync(0xffffffffu, v2b, 1);
      if (lane == 0) {
        if (s == 0) {
          nb1 = BIGF;
          nb2 = (p == 0) ? 0.0f : BIGF;
        } else {
          nb1 = rv[j];
          nb2 = (j == 0) ? rcarry : rv[j - 1];
        }
      }
      // row row0:   dd=nb2, up=nb1, lf=v1a
      // row row0+1: dd=v2a, up=v1a, lf=v1b
      float sm0 = softmin3s(nb2, nb1, v1a);
      float sm1 = softmin3s(v2a, v1a, v1b);
      unsigned pr = (unsigned)(p - row0);
      float n0 = (pr      < (unsigned)SEQ) ? fmaf(cur[j].x, L2E, sm0) : BIGF;
      float n1 = (pr - 1u < (unsigned)SEQ) ? fmaf(cur[j].y, L2E, sm1) : BIGF;
      v2a = v1a; v2b = v1b; v1a = n0; v1b = n1;
      if (s < STAGES - 1 && lane == 31) bmy[p] = v1b;   // plain store; flag release orders it
    }
    if (s < STAGES - 1 && lane == 31) {
      asm volatile("st.release.gpu.global.b32 [%0], %1;"
                   :: "l"(fmy), "r"((unsigned)(g + 1)) : "memory");
    }
    rcarry = rv[7];
#pragma unroll
    for (int j = 0; j < 8; j++) { cur[j] = nxt[j]; nxt[j] = pf[j]; rv[j] = rvn[j]; }
  }

  // 128*8 = 1024 steps; last real diagonal is p = 1022, so the final cell's
  // value (row 511 at p=1022) sits in v2b after the extra masked step p=1023.
  if (s == STAGES - 1 && lane == 31) out[b] = v2b * LN2;
#undef LOADD
#undef WAITFLAG
#undef LOADRING
}

// ---------------------------------------------------------------------------
extern "C" void kernel_launch(void* const* d_in, const int* in_sizes, int n_in,
                              void* d_out, int out_size) {
  const float* X = (const float*)d_in[0];
  const float* Y = (const float*)d_in[1];
  float* out = (float*)d_out;

  dim3 grid_g(SEQ / TI, SEQ / TJ, BATCH);
  gemm_diag_kernel<<<grid_g, 128>>>(X, Y);

  dim3 grid_dp(BATCH, STAGES);
  softdtw_dp_kernel<<<grid_dp, 32>>>(out);
}

// round 4
// speedup vs baseline: 2.1362x; 2.1362x over previous
#include <cuda_runtime.h>
#include <cstdint>

#define BATCH 32
#define SEQ   512
#define DIMK  64
#define DPITCH 1024
#define BIGF  1e30f
#define L2E   1.4426950408889634f
#define LN2   0.6931471805599453f

// Diagonal-major distance scratch: Ddiag[b][p][i] = D[b, i, p-i]  (64 MB)
__device__ float g_Ddiag[BATCH * DPITCH * SEQ];

// ---------------------------------------------------------------------------
// Phase 1: D = x2 + y2 - 2 x.y, written diagonal-major with coalesced stores.
// 256 threads: halves split the 16 j-blocks (8 each).
// ---------------------------------------------------------------------------
#define TI 128
#define TJ 128
#define YS_STRIDE 132
#define DST_STRIDE 9

__global__ __launch_bounds__(256) void gemm_diag_kernel(
    const float* __restrict__ X, const float* __restrict__ Y) {
  const int t    = threadIdx.x;
  const int half = t >> 7;
  const int tt   = t & 127;
  const int i0 = blockIdx.x * TI;
  const int j0 = blockIdx.y * TJ;
  const int b  = blockIdx.z;

  __shared__ float Ys[DIMK * YS_STRIDE];     // [k][j]
  __shared__ float y2s[TJ];
  __shared__ float Dst[2][TI * DST_STRIDE];  // per-half staging

  const float* Xb = X + ((size_t)b * SEQ + i0) * DIMK;
  const float* Yb = Y + ((size_t)b * SEQ + j0) * DIMK;

  for (int e = t; e < TJ * DIMK; e += 256) {
    int j = e >> 6;
    int k = e & 63;
    Ys[k * YS_STRIDE + j] = Yb[e];
  }

  float xr[DIMK];
  float x2 = 0.f;
#pragma unroll
  for (int k4 = 0; k4 < DIMK; k4 += 4) {
    float4 v = *reinterpret_cast<const float4*>(Xb + (size_t)tt * DIMK + k4);
    xr[k4] = v.x; xr[k4 + 1] = v.y; xr[k4 + 2] = v.z; xr[k4 + 3] = v.w;
  }
#pragma unroll
  for (int k = 0; k < DIMK; k++) x2 += xr[k] * xr[k];

  __syncthreads();

  if (half == 0) {
    float a = 0.f;
#pragma unroll
    for (int k = 0; k < DIMK; k++) {
      float yv = Ys[k * YS_STRIDE + tt];
      a += yv * yv;
    }
    y2s[tt] = a;
  }
  __syncthreads();

  float* gout = g_Ddiag + (size_t)b * (DPITCH * SEQ);
  const int w = tt >> 5, lane = tt & 31;

  for (int jj = 0; jj < 8; jj++) {
    const int jb = half * 8 + jj;
    float acc[8];
#pragma unroll
    for (int m = 0; m < 8; m++) acc[m] = 0.f;

#pragma unroll
    for (int k = 0; k < DIMK; k++) {
      const float4 ya = *reinterpret_cast<const float4*>(&Ys[k * YS_STRIDE + jb * 8]);
      const float4 yb = *reinterpret_cast<const float4*>(&Ys[k * YS_STRIDE + jb * 8 + 4]);
      const float xv = xr[k];
      acc[0] += xv * ya.x; acc[1] += xv * ya.y;
      acc[2] += xv * ya.z; acc[3] += xv * ya.w;
      acc[4] += xv * yb.x; acc[5] += xv * yb.y;
      acc[6] += xv * yb.z; acc[7] += xv * yb.w;
    }

#pragma unroll
    for (int m = 0; m < 8; m++) {
      Dst[half][tt * DST_STRIDE + m] = x2 + y2s[jb * 8 + m] - 2.f * acc[m];
    }
    __syncthreads();

    const int p0 = i0 + j0 + jb * 8;
    for (int dbase = w * 4; dbase < TI + 8 - 1; dbase += 16) {
      int d = dbase + (lane >> 3);
      int q = lane & 7;
      if (d < TI + 8 - 1) {
        int lo = d - 7 < 0 ? 0 : d - 7;
        int hi = d < TI - 1 ? d : TI - 1;
        int irow = lo + q;
        if (irow <= hi) {
          gout[(size_t)(p0 + d) * SEQ + (i0 + irow)] =
              Dst[half][irow * DST_STRIDE + (d - irow)];
        }
      }
    }
    __syncthreads();
  }
}

// ---------------------------------------------------------------------------
// Phase 2: wavefront DP, trapezoid-blocked. 4 warps; warp w owns rows
// [128w-32, 128w+127] (top 32 redundant). Lane l owns rows win + l + 32k,
// k = 0..4. All per-step neighbor traffic = 5 wrap-shuffles; inter-warp
// exchange (slot4 -> slot0) + 2 barriers only every 32 diagonals.
// Base-2 scaled domain (R' = R * log2e).
// ---------------------------------------------------------------------------
__device__ __forceinline__ float ex2f(float x) {
  float r; asm("ex2.approx.f32 %0, %1;" : "=f"(r) : "f"(x)); return r;
}
__device__ __forceinline__ float lg2f(float x) {
  float r; asm("lg2.approx.f32 %0, %1;" : "=f"(r) : "f"(x)); return r;
}
__device__ __forceinline__ float softmin3s(float a, float b, float c) {
  float u = fminf(a, b), v = fmaxf(a, b);
  float mn = fminf(u, c);
  float mx = fmaxf(v, c);
  float md = fmaxf(u, fminf(v, c));
  float s = 1.0f + ex2f(mn - md) + ex2f(mn - mx);
  return mn - lg2f(s);
}

__global__ __launch_bounds__(128) void softdtw_dp_kernel(float* __restrict__ out) {
  const int b = blockIdx.x;
  const int t = threadIdx.x;
  const int lane = t & 31, w = t >> 5;
  const int rw = 128 * w - 32 + lane;          // slot k -> row rw + 32k
  const int src = (lane + 31) & 31;            // wrap shuffle source

  __shared__ float xch1[4][32];
  __shared__ float xch2[4][32];

  bool vr[5];
#pragma unroll
  for (int k = 0; k < 5; k++) vr[k] = ((unsigned)(rw + 32 * k) < (unsigned)SEQ);

  const float* __restrict__ base = g_Ddiag + (size_t)b * (DPITCH * SEQ);

  float v1[5], v2[5], nb2[5];
#pragma unroll
  for (int k = 0; k < 5; k++) { v1[k] = BIGF; v2[k] = BIGF; nb2[k] = BIGF; }
  // corner: R(0,0) = D[0][0]; row 0 = (warp 0, lane 0, slot 1)
  if (w == 0 && lane == 0) v1[1] = base[0] * L2E;

  // one DP step on diagonal P with D values D5[0..4]
#define STEP(P, D5)                                                           \
  {                                                                           \
    float s0 = __shfl_sync(0xffffffffu, v1[0], src);                          \
    float s1 = __shfl_sync(0xffffffffu, v1[1], src);                          \
    float s2 = __shfl_sync(0xffffffffu, v1[2], src);                          \
    float s3 = __shfl_sync(0xffffffffu, v1[3], src);                          \
    float s4 = __shfl_sync(0xffffffffu, v1[4], src);                          \
    float nb1_0 = (lane == 0) ? BIGF : s0;                                    \
    float nb1_1 = (lane == 0) ? s0 : s1;                                      \
    float nb1_2 = (lane == 0) ? s1 : s2;                                      \
    float nb1_3 = (lane == 0) ? s2 : s3;                                      \
    float nb1_4 = (lane == 0) ? s3 : s4;                                      \
    float sm0 = softmin3s(nb2[0], nb1_0, v1[0]);                              \
    float sm1 = softmin3s(nb2[1], nb1_1, v1[1]);                              \
    float sm2 = softmin3s(nb2[2], nb1_2, v1[2]);                              \
    float sm3 = softmin3s(nb2[3], nb1_3, v1[3]);                              \
    float sm4 = softmin3s(nb2[4], nb1_4, v1[4]);                              \
    unsigned p0_ = (unsigned)((P) - (rw));                                    \
    unsigned p1_ = (unsigned)((P) - (rw + 32));                               \
    unsigned p2_ = (unsigned)((P) - (rw + 64));                               \
    unsigned p3_ = (unsigned)((P) - (rw + 96));                               \
    unsigned p4_ = (unsigned)((P) - (rw + 128));                              \
    float n0 = (vr[0] && p0_ < (unsigned)SEQ) ? fmaf((D5)[0], L2E, sm0) : BIGF; \
    float n1 = (vr[1] && p1_ < (unsigned)SEQ) ? fmaf((D5)[1], L2E, sm1) : BIGF; \
    float n2 = (vr[2] && p2_ < (unsigned)SEQ) ? fmaf((D5)[2], L2E, sm2) : BIGF; \
    float n3 = (vr[3] && p3_ < (unsigned)SEQ) ? fmaf((D5)[3], L2E, sm3) : BIGF; \
    float n4 = (vr[4] && p4_ < (unsigned)SEQ) ? fmaf((D5)[4], L2E, sm4) : BIGF; \
    v2[0] = v1[0]; v2[1] = v1[1]; v2[2] = v1[2]; v2[3] = v1[3]; v2[4] = v1[4]; \
    v1[0] = n0; v1[1] = n1; v1[2] = n2; v1[3] = n3; v1[4] = n4;               \
    nb2[0] = nb1_0; nb2[1] = nb1_1; nb2[2] = nb1_2;                           \
    nb2[3] = nb1_3; nb2[4] = nb1_4;                                           \
  }

  // inter-warp exchange: warp w-1 slot4 -> warp w slot0; rebuild nb2 from v2
#define EXCHANGE()                                                            \
  {                                                                           \
    __syncthreads();                                                          \
    if (w < 3) { xch1[w + 1][lane] = v1[4]; xch2[w + 1][lane] = v2[4]; }      \
    __syncthreads();                                                          \
    if (w > 0) { v1[0] = xch1[w][lane]; v2[0] = xch2[w][lane]; }              \
    float t0 = __shfl_sync(0xffffffffu, v2[0], src);                          \
    float t1 = __shfl_sync(0xffffffffu, v2[1], src);                          \
    float t2 = __shfl_sync(0xffffffffu, v2[2], src);                          \
    float t3 = __shfl_sync(0xffffffffu, v2[3], src);                          \
    float t4 = __shfl_sync(0xffffffffu, v2[4], src);                          \
    nb2[0] = (lane == 0) ? BIGF : t0;                                         \
    nb2[1] = (lane == 0) ? t0 : t1;                                           \
    nb2[2] = (lane == 0) ? t1 : t2;                                           \
    nb2[3] = (lane == 0) ? t2 : t3;                                           \
    nb2[4] = (lane == 0) ? t3 : t4;                                           \
  }

  // load D group H (8 diagonals p = 8H+1 .. 8H+8, clamped) into BUF[8][5]
#define LOADG(H, BUF)                                                         \
  {                                                                           \
    _Pragma("unroll") for (int j_ = 0; j_ < 8; j_++) {                        \
      int p_ = 8 * (H) + 1 + j_;                                              \
      if (p_ > 1022) p_ = 1022;                                               \
      const float* a_ = base + (size_t)p_ * SEQ + rw;                         \
      (BUF)[j_][0] = __ldg(a_);                                               \
      (BUF)[j_][1] = __ldg(a_ + 32);                                          \
      (BUF)[j_][2] = __ldg(a_ + 64);                                          \
      (BUF)[j_][3] = __ldg(a_ + 96);                                          \
      (BUF)[j_][4] = __ldg(a_ + 128);                                         \
    }                                                                         \
  }

#define PROC(H, BUF)                                                          \
  {                                                                           \
    _Pragma("unroll") for (int j_ = 0; j_ < 8; j_++) {                        \
      STEP(8 * (H) + 1 + j_, (BUF)[j_]);                                      \
    }                                                                         \
    if (((H) & 3) == 3) EXCHANGE();                                           \
  }

  float A[8][5], B[8][5];
  LOADG(0, A);
  for (int hh = 0; hh < 126; hh += 2) {
    LOADG(hh + 1, B);
    PROC(hh, A);
    LOADG(hh + 2, A);
    PROC(hh + 1, B);
  }
  // group 126 (p = 1009..1016) from A; preload tail into B
  LOADG(127, B);
  PROC(126, A);
  // tail: p = 1017..1022
#pragma unroll
  for (int j = 0; j < 6; j++) {
    STEP(1017 + j, B[j]);
  }

  // R(511, 511) at diag 1022 = warp 3, slot 4, lane 31
  if (w == 3 && lane == 31) out[b] = v1[4] * LN2;
#undef STEP
#undef EXCHANGE
#undef LOADG
#undef PROC
}

// ---------------------------------------------------------------------------
extern "C" void kernel_launch(void* const* d_in, const int* in_sizes, int n_in,
                              void* d_out, int out_size) {
  const float* X = (const float*)d_in[0];
  const float* Y = (const float*)d_in[1];
  float* out = (float*)d_out;

  dim3 grid_g(SEQ / TI, SEQ / TJ, BATCH);
  gemm_diag_kernel<<<grid_g, 256>>>(X, Y);
  softdtw_dp_kernel<<<BATCH, 128>>>(out);
}

// round 5
// speedup vs baseline: 2.2073x; 1.0333x over previous
#include <cuda_runtime.h>
#include <cstdint>

#define BATCH 32
#define SEQ   512
#define DIMK  64
#define DPITCH 1024
#define BIGF  1e30f
#define L2E   1.4426950408889634f
#define LN2   0.6931471805599453f

// Diagonal-major distance scratch: Ddiag[b][p][i] = D[b, i, p-i]  (64 MB)
__device__ float g_Ddiag[BATCH * DPITCH * SEQ];

// ---------------------------------------------------------------------------
// Phase 1: D = x2 + y2 - 2 x.y, written diagonal-major with coalesced stores.
// (unchanged from Round 4 — known good)
// ---------------------------------------------------------------------------
#define TI 128
#define TJ 128
#define YS_STRIDE 132
#define DST_STRIDE 9

__global__ __launch_bounds__(256) void gemm_diag_kernel(
    const float* __restrict__ X, const float* __restrict__ Y) {
  const int t    = threadIdx.x;
  const int half = t >> 7;
  const int tt   = t & 127;
  const int i0 = blockIdx.x * TI;
  const int j0 = blockIdx.y * TJ;
  const int b  = blockIdx.z;

  __shared__ float Ys[DIMK * YS_STRIDE];     // [k][j]
  __shared__ float y2s[TJ];
  __shared__ float Dst[2][TI * DST_STRIDE];  // per-half staging

  const float* Xb = X + ((size_t)b * SEQ + i0) * DIMK;
  const float* Yb = Y + ((size_t)b * SEQ + j0) * DIMK;

  for (int e = t; e < TJ * DIMK; e += 256) {
    int j = e >> 6;
    int k = e & 63;
    Ys[k * YS_STRIDE + j] = Yb[e];
  }

  float xr[DIMK];
  float x2 = 0.f;
#pragma unroll
  for (int k4 = 0; k4 < DIMK; k4 += 4) {
    float4 v = *reinterpret_cast<const float4*>(Xb + (size_t)tt * DIMK + k4);
    xr[k4] = v.x; xr[k4 + 1] = v.y; xr[k4 + 2] = v.z; xr[k4 + 3] = v.w;
  }
#pragma unroll
  for (int k = 0; k < DIMK; k++) x2 += xr[k] * xr[k];

  __syncthreads();

  if (half == 0) {
    float a = 0.f;
#pragma unroll
    for (int k = 0; k < DIMK; k++) {
      float yv = Ys[k * YS_STRIDE + tt];
      a += yv * yv;
    }
    y2s[tt] = a;
  }
  __syncthreads();

  float* gout = g_Ddiag + (size_t)b * (DPITCH * SEQ);
  const int w = tt >> 5, lane = tt & 31;

  for (int jj = 0; jj < 8; jj++) {
    const int jb = half * 8 + jj;
    float acc[8];
#pragma unroll
    for (int m = 0; m < 8; m++) acc[m] = 0.f;

#pragma unroll
    for (int k = 0; k < DIMK; k++) {
      const float4 ya = *reinterpret_cast<const float4*>(&Ys[k * YS_STRIDE + jb * 8]);
      const float4 yb = *reinterpret_cast<const float4*>(&Ys[k * YS_STRIDE + jb * 8 + 4]);
      const float xv = xr[k];
      acc[0] += xv * ya.x; acc[1] += xv * ya.y;
      acc[2] += xv * ya.z; acc[3] += xv * ya.w;
      acc[4] += xv * yb.x; acc[5] += xv * yb.y;
      acc[6] += xv * yb.z; acc[7] += xv * yb.w;
    }

#pragma unroll
    for (int m = 0; m < 8; m++) {
      Dst[half][tt * DST_STRIDE + m] = x2 + y2s[jb * 8 + m] - 2.f * acc[m];
    }
    __syncthreads();

    const int p0 = i0 + j0 + jb * 8;
    for (int dbase = w * 4; dbase < TI + 8 - 1; dbase += 16) {
      int d = dbase + (lane >> 3);
      int q = lane & 7;
      if (d < TI + 8 - 1) {
        int lo = d - 7 < 0 ? 0 : d - 7;
        int hi = d < TI - 1 ? d : TI - 1;
        int irow = lo + q;
        if (irow <= hi) {
          gout[(size_t)(p0 + d) * SEQ + (i0 + irow)] =
              Dst[half][irow * DST_STRIDE + (d - irow)];
        }
      }
    }
    __syncthreads();
  }
}

// ---------------------------------------------------------------------------
// Phase 2: warp-skewed systolic wavefront DP.
// 4 warps; warp w owns rows [128w, 128w+127], 4 consecutive rows per thread,
// and at global step P processes diagonal pc = P - 10w. Inter-warp boundary
// flows through a 16-deep smem ring read 11/12 steps after write; barriers
// only every 8 steps. Out-of-range-right cells freeze so the final value
// survives the pipeline drain. Base-2 scaled domain.
// ---------------------------------------------------------------------------
__device__ __forceinline__ float ex2f(float x) {
  float r; asm("ex2.approx.f32 %0, %1;" : "=f"(r) : "f"(x)); return r;
}
__device__ __forceinline__ float lg2f(float x) {
  float r; asm("lg2.approx.f32 %0, %1;" : "=f"(r) : "f"(x)); return r;
}
__device__ __forceinline__ float softmin3s(float a, float b, float c) {
  float u = fminf(a, b), v = fmaxf(a, b);
  float mn = fminf(u, c);
  float mx = fmaxf(v, c);
  float md = fmaxf(u, fminf(v, c));
  float s = 1.0f + ex2f(mn - md) + ex2f(mn - mx);
  return mn - lg2f(s);
}

#define NGROUP 132   // 132*8 = 1056 steps >= 1052 (last useful step)

__global__ __launch_bounds__(128) void softdtw_dp_kernel(float* __restrict__ out) {
  const int b = blockIdx.x;
  const int t = threadIdx.x;
  const int lane = t & 31, w = t >> 5;

  __shared__ float ring[4][16];
  if (t < 64) (&ring[0][0])[t] = BIGF;

  const float* __restrict__ base = g_Ddiag + (size_t)b * (DPITCH * SEQ);
  const int col   = 128 * w + 4 * lane;   // first row owned by this thread
  const int rbase = 138 * w + 4 * lane;   // jj(slot0) = P - rbase

  float v1[4], v2[4];
#pragma unroll
  for (int s = 0; s < 4; s++) { v1[s] = BIGF; v2[s] = BIGF; }

  __syncthreads();

  // D prefetch: warp w at step P needs diag row P - 10w, columns col..col+3.
  float4 cur[8], nxt[8];
#define LOADG(G, BUF)                                                         \
  {                                                                           \
    _Pragma("unroll") for (int j_ = 0; j_ < 8; j_++) {                        \
      int r_ = 8 * (G) + j_ - 10 * w;                                         \
      r_ = r_ < 0 ? 0 : (r_ > 1023 ? 1023 : r_);                              \
      (BUF)[j_] = *reinterpret_cast<const float4*>(base + (size_t)r_ * SEQ + col); \
    }                                                                         \
  }

  LOADG(0, cur);

  for (int g = 0; g < NGROUP; ++g) {
    if (g + 1 < NGROUP) LOADG(g + 1, nxt);

#pragma unroll
    for (int j = 0; j < 8; ++j) {
      const int P = 8 * g + j;
      // neighbor row (first row - 1) at diag pc-1 (up) and pc-2 (dd)
      float up = __shfl_up_sync(0xffffffffu, v1[3], 1);
      float dd = __shfl_up_sync(0xffffffffu, v2[3], 1);
      if (lane == 0) {
        if (w == 0) {
          up = BIGF;
          dd = (P == 0) ? 0.0f : BIGF;   // virtual R(-1,-1)=0 for the corner
        } else {
          up = ring[w][(P + 5) & 15];    // written at step P-11 by warp w-1
          dd = ring[w][(P + 4) & 15];    // written at step P-12
        }
      }
      float sm0 = softmin3s(dd,    up,    v1[0]);
      float sm1 = softmin3s(v2[0], v1[0], v1[1]);
      float sm2 = softmin3s(v2[1], v1[1], v1[2]);
      float sm3 = softmin3s(v2[2], v1[2], v1[3]);
      const int c0 = P - rbase;
      const float dv0 = cur[j].x, dv1 = cur[j].y, dv2 = cur[j].z, dv3 = cur[j].w;

      // slot 0
      {
        int jj = c0;
        float nv  = (jj < 0) ? BIGF : ((jj < 512) ? fmaf(dv0, L2E, sm0) : v1[0]);
        float v2n = (jj >= 512) ? v2[0] : v1[0];
        v2[0] = v2n; v1[0] = nv;
      }
      // slot 1
      {
        int jj = c0 - 1;
        float nv  = (jj < 0) ? BIGF : ((jj < 512) ? fmaf(dv1, L2E, sm1) : v1[1]);
        float v2n = (jj >= 512) ? v2[1] : v1[1];
        v2[1] = v2n; v1[1] = nv;
      }
      // slot 2
      {
        int jj = c0 - 2;
        float nv  = (jj < 0) ? BIGF : ((jj < 512) ? fmaf(dv2, L2E, sm2) : v1[2]);
        float v2n = (jj >= 512) ? v2[2] : v1[2];
        v2[2] = v2n; v1[2] = nv;
      }
      // slot 3
      {
        int jj = c0 - 3;
        float nv  = (jj < 0) ? BIGF : ((jj < 512) ? fmaf(dv3, L2E, sm3) : v1[3]);
        float v2n = (jj >= 512) ? v2[3] : v1[3];
        v2[3] = v2n; v1[3] = nv;
      }

      if (w < 3 && lane == 31) ring[w + 1][P & 15] = v1[3];
    }

    __syncthreads();   // orders ring STS (gap 11/12 > 8) once per 8 steps
#pragma unroll
    for (int j = 0; j < 8; ++j) cur[j] = nxt[j];
  }

  // thread 127 slot 3 = row 511; frozen at its last valid diag 1022.
  if (t == 127) out[b] = v1[3] * LN2;
#undef LOADG
}

// ---------------------------------------------------------------------------
extern "C" void kernel_launch(void* const* d_in, const int* in_sizes, int n_in,
                              void* d_out, int out_size) {
  const float* X = (const float*)d_in[0];
  const float* Y = (const float*)d_in[1];
  float* out = (float*)d_out;

  dim3 grid_g(SEQ / TI, SEQ / TJ, BATCH);
  gemm_diag_kernel<<<grid_g, 256>>>(X, Y);
  softdtw_dp_kernel<<<BATCH, 128>>>(out);
}